// round 2
// baseline (speedup 1.0000x reference)
#include <cuda_runtime.h>
#include <cstdint>

// ---------------- scratch (no allocation allowed -> __device__ globals) ------
__device__ float g_hq[4194304];      // quantized-dequantized activations
__device__ float g_wq[1048576];
__device__ float g_wk[1048576];
__device__ float g_wv[1048576];
__device__ float g_Q[4194304];       // [B*H, S, 64]
__device__ float g_K[4194304];
__device__ float g_V[4194304];
__device__ unsigned int g_absmax[4]; // 0:hidden 1:Wq 2:Wk 3:Wv

// ---------------- small kernels ---------------------------------------------
__global__ void init_k() {
    if (threadIdx.x < 4) g_absmax[threadIdx.x] = 0u;
}

__global__ void absmax_k(const float* __restrict__ x, int n, int slot) {
    float m = 0.f;
    for (int i = blockIdx.x * blockDim.x + threadIdx.x; i < n; i += gridDim.x * blockDim.x)
        m = fmaxf(m, fabsf(x[i]));
#pragma unroll
    for (int o = 16; o > 0; o >>= 1) m = fmaxf(m, __shfl_xor_sync(0xffffffffu, m, o));
    if ((threadIdx.x & 31) == 0) atomicMax(&g_absmax[slot], __float_as_uint(m));
}

__global__ void quant_act_k(const float* __restrict__ x, float* __restrict__ y, int n) {
    float s = fmaxf(__uint_as_float(g_absmax[0]), 1e-8f) / 127.0f;
    for (int i = blockIdx.x * blockDim.x + threadIdx.x; i < n; i += gridDim.x * blockDim.x) {
        float v = rintf(x[i] / s);          // jnp.round = round-half-even = rintf
        v = fminf(fmaxf(v, -127.f), 127.f);
        y[i] = v * s;
    }
}

__global__ void quant_w_k(const float* __restrict__ x, float* __restrict__ y, int n, int slot) {
    float s = fmaxf(__uint_as_float(g_absmax[slot]), 1e-8f) / 7.0f;
    for (int i = blockIdx.x * blockDim.x + threadIdx.x; i < n; i += gridDim.x * blockDim.x) {
        float v = rintf(x[i] / s);
        v = fminf(fmaxf(v, -7.f), 7.f);
        y[i] = v * s;
    }
}

// ---------------- GEMM: C[m,n] = sum_d A[m,d]*W[n,d] ------------------------
// 128x128 tile, BK=8, 256 threads, 8x8 per thread. Output written head-split:
// Out[((b*16+h)*1024 + s)*64 + dh]
__global__ __launch_bounds__(256) void gemm128(
    const float* __restrict__ A0, const float* __restrict__ A1, const float* __restrict__ A2,
    const float* __restrict__ W0, const float* __restrict__ W1, const float* __restrict__ W2,
    float* __restrict__ O0, float* __restrict__ O1, float* __restrict__ O2)
{
    __shared__ float As[8][128];
    __shared__ float Bs[8][128];

    const float* A = (blockIdx.z == 0) ? A0 : (blockIdx.z == 1) ? A1 : A2;
    const float* W = (blockIdx.z == 0) ? W0 : (blockIdx.z == 1) ? W1 : W2;
    float*       O = (blockIdx.z == 0) ? O0 : (blockIdx.z == 1) ? O1 : O2;

    int tid = threadIdx.x;
    int m0 = blockIdx.y * 128, n0 = blockIdx.x * 128;
    int tx = tid & 15, ty = tid >> 4;

    int lrow = tid >> 1;          // 0..127
    int lk   = (tid & 1) * 4;     // 0 or 4
    const float* Ag = A + (m0 + lrow) * 1024 + lk;
    const float* Wg = W + (n0 + lrow) * 1024 + lk;

    float c[8][8] = {};

    for (int kt = 0; kt < 1024; kt += 8) {
        float4 av = *(const float4*)(Ag + kt);
        float4 wv = *(const float4*)(Wg + kt);
        As[lk + 0][lrow] = av.x; As[lk + 1][lrow] = av.y;
        As[lk + 2][lrow] = av.z; As[lk + 3][lrow] = av.w;
        Bs[lk + 0][lrow] = wv.x; Bs[lk + 1][lrow] = wv.y;
        Bs[lk + 2][lrow] = wv.z; Bs[lk + 3][lrow] = wv.w;
        __syncthreads();
#pragma unroll
        for (int k = 0; k < 8; k++) {
            float4 a0 = *(const float4*)&As[k][ty * 8];
            float4 a1 = *(const float4*)&As[k][ty * 8 + 4];
            float4 b0 = *(const float4*)&Bs[k][tx * 8];
            float4 b1 = *(const float4*)&Bs[k][tx * 8 + 4];
            float a[8] = {a0.x, a0.y, a0.z, a0.w, a1.x, a1.y, a1.z, a1.w};
            float b[8] = {b0.x, b0.y, b0.z, b0.w, b1.x, b1.y, b1.z, b1.w};
#pragma unroll
            for (int i = 0; i < 8; i++)
#pragma unroll
                for (int j = 0; j < 8; j++)
                    c[i][j] = fmaf(a[i], b[j], c[i][j]);
        }
        __syncthreads();
    }

#pragma unroll
    for (int i = 0; i < 8; i++) {
        int m = m0 + ty * 8 + i;
        int bb = m >> 10, s = m & 1023;
#pragma unroll
        for (int j = 0; j < 8; j++) {
            int n = n0 + tx * 8 + j;
            int h = n >> 6, dh = n & 63;
            O[((bb * 16 + h) << 16) + (s << 6) + dh] = c[i][j];
        }
    }
}

// ---------------- JAX threefry2x32 noise (key = (0,42)) ---------------------
// PARTITIONABLE stream (jax_threefry_partitionable=True, default in jax>=0.4.36):
//   counts = iota(uint64, n); per element i:
//     (o0,o1) = threefry2x32(key, c0 = hi32(i) = 0, c1 = lo32(i) = i)
//     bits[i] = o0 ^ o1
__device__ __forceinline__ uint32_t rotl32(uint32_t x, int r) {
    return (x << r) | (x >> (32 - r));
}

__device__ __forceinline__ void threefry2x32(uint32_t c0, uint32_t c1,
                                             uint32_t& o0, uint32_t& o1) {
    const uint32_t k0 = 0u, k1 = 42u, k2 = 0u ^ 42u ^ 0x1BD11BDAu;
    uint32_t x0 = c0 + k0, x1 = c1 + k1;
#define TF_R(r) { x0 += x1; x1 = rotl32(x1, r); x1 ^= x0; }
    TF_R(13) TF_R(15) TF_R(26) TF_R(6)
    x0 += k1; x1 += k2 + 1u;
    TF_R(17) TF_R(29) TF_R(16) TF_R(24)
    x0 += k2; x1 += k0 + 2u;
    TF_R(13) TF_R(15) TF_R(26) TF_R(6)
    x0 += k0; x1 += k1 + 3u;
    TF_R(17) TF_R(29) TF_R(16) TF_R(24)
    x0 += k1; x1 += k2 + 4u;
    TF_R(13) TF_R(15) TF_R(26) TF_R(6)
    x0 += k2; x1 += k0 + 5u;
#undef TF_R
    o0 = x0; o1 = x1;
}

__device__ __forceinline__ float noise_at(unsigned int i) {
    uint32_t o0, o1;
    threefry2x32(0u, i, o0, o1);          // c0 = hi32(counter)=0, c1 = lo32 = i
    uint32_t bits = o0 ^ o1;              // 32-bit output width combine
    // uniform in [lo, 1): f in [0,1) from top-23 bits
    float f = __uint_as_float((bits >> 9) | 0x3f800000u) - 1.0f;
    const float lo = -0.99999994f;           // nextafter(-1,0)
    const float span = 1.0f - lo;            // == 2.0f in fp32 (ties-to-even)
    float u = fmaxf(lo, fmaf(f, span, lo));
    // erfinv, XLA/Giles f32 polynomial
    float w = -log1pf(-u * u);
    float p;
    if (w < 5.0f) {
        w = w - 2.5f;
        p = 2.81022636e-08f;
        p = fmaf(p, w, 3.43273939e-07f);
        p = fmaf(p, w, -3.5233877e-06f);
        p = fmaf(p, w, -4.39150654e-06f);
        p = fmaf(p, w, 0.00021858087f);
        p = fmaf(p, w, -0.00125372503f);
        p = fmaf(p, w, -0.00417768164f);
        p = fmaf(p, w, 0.246640727f);
        p = fmaf(p, w, 1.50140941f);
    } else {
        w = sqrtf(w) - 3.0f;
        p = -0.000200214257f;
        p = fmaf(p, w, 0.000100950558f);
        p = fmaf(p, w, 0.00134934322f);
        p = fmaf(p, w, -0.00367342844f);
        p = fmaf(p, w, 0.00573950773f);
        p = fmaf(p, w, -0.0076224613f);
        p = fmaf(p, w, 0.00943887047f);
        p = fmaf(p, w, 1.00167406f);
        p = fmaf(p, w, 2.83297682f);
    }
    return 1.41421356f * (p * u) * 0.05f;    // sqrt(2)*erfinv(u) * QKT_STD
}

// ---------------- fused flash attention + noise + mask ----------------------
// grid (64 bh, 16 q-tiles), 256 threads (8 warps x 8 q-rows each).
// dynamic smem: Qs[64][64] | Kt[64][65] (d-major) | Vs[64][64]
__global__ __launch_bounds__(256) void attn_k(
    const float* __restrict__ Q, const float* __restrict__ K,
    const float* __restrict__ V, const float* __restrict__ mask,
    float* __restrict__ out)
{
    extern __shared__ float sm[];
    float* Qs = sm;                    // 4096
    float* Kt = sm + 4096;             // 64*65 = 4160
    float* Vs = sm + 4096 + 4160;      // 4096

    int bh = blockIdx.x, qt = blockIdx.y;
    int b = bh >> 4, h = bh & 15;
    int tid = threadIdx.x, warp = tid >> 5, lane = tid & 31;

    const float* Qg = Q + (bh * 1024 + qt * 64) * 64;
    for (int i = tid; i < 4096; i += 256) Qs[i] = Qg[i];

    float m_r[8], l_r[8], acc0[8], acc1[8];
#pragma unroll
    for (int r = 0; r < 8; r++) { m_r[r] = -1e30f; l_r[r] = 0.f; acc0[r] = 0.f; acc1[r] = 0.f; }

    const float* maskb = mask + (b << 10);

#pragma unroll 1
    for (int ktile = 0; ktile < 16; ktile++) {
        __syncthreads();
        const float* Kg = K + (bh * 1024 + ktile * 64) * 64;
        const float* Vg = V + (bh * 1024 + ktile * 64) * 64;
        for (int i = tid; i < 4096; i += 256) {
            int kk = i >> 6, d = i & 63;
            Kt[d * 65 + kk] = Kg[i];
            Vs[i] = Vg[i];
        }
        __syncthreads();

        int kg0 = (ktile << 6) + lane;
        float mv0 = maskb[kg0], mv1 = maskb[kg0 + 32];

#pragma unroll 1
        for (int r = 0; r < 8; r++) {
            int ql = (warp << 3) + r;
            const float* qrow = Qs + (ql << 6);
            float s0 = 0.f, s1 = 0.f;
#pragma unroll
            for (int d = 0; d < 64; d++) {
                float qd = qrow[d];
                s0 = fmaf(qd, Kt[d * 65 + lane], s0);
                s1 = fmaf(qd, Kt[d * 65 + lane + 32], s1);
            }
            int qg = (qt << 6) + ql;
            unsigned int idx0 = ((unsigned)bh << 20) + ((unsigned)qg << 10) + (unsigned)kg0;
            s0 = fmaf(s0, 0.125f, noise_at(idx0) + mv0);
            s1 = fmaf(s1, 0.125f, noise_at(idx0 + 32u) + mv1);

            float tm = fmaxf(s0, s1);
#pragma unroll
            for (int o = 16; o > 0; o >>= 1) tm = fmaxf(tm, __shfl_xor_sync(0xffffffffu, tm, o));
            float mnew = fmaxf(m_r[r], tm);
            float corr = __expf(m_r[r] - mnew);
            float p0 = __expf(s0 - mnew), p1 = __expf(s1 - mnew);
            float psum = p0 + p1;
#pragma unroll
            for (int o = 16; o > 0; o >>= 1) psum += __shfl_xor_sync(0xffffffffu, psum, o);
            l_r[r] = l_r[r] * corr + psum;
            m_r[r] = mnew;

            float a0 = acc0[r] * corr, a1 = acc1[r] * corr;
#pragma unroll
            for (int kk2 = 0; kk2 < 32; kk2++) {
                float pa = __shfl_sync(0xffffffffu, p0, kk2);
                float pb = __shfl_sync(0xffffffffu, p1, kk2);
                a0 = fmaf(pa, Vs[(kk2 << 6) + lane], a0);
                a1 = fmaf(pa, Vs[(kk2 << 6) + lane + 32], a1);
                a0 = fmaf(pb, Vs[((kk2 + 32) << 6) + lane], a0);
                a1 = fmaf(pb, Vs[((kk2 + 32) << 6) + lane + 32], a1);
            }
            acc0[r] = a0; acc1[r] = a1;
        }
    }

#pragma unroll
    for (int r = 0; r < 8; r++) {
        int ql = (warp << 3) + r;
        int s = (qt << 6) + ql;
        float inv = 1.0f / l_r[r];
        float* o = out + ((b << 10) + s) * 1024 + (h << 6);
        o[lane]      = acc0[r] * inv;
        o[lane + 32] = acc1[r] * inv;
    }
}

// ---------------- launch -----------------------------------------------------
extern "C" void kernel_launch(void* const* d_in, const int* in_sizes, int n_in,
                              void* d_out, int out_size) {
    const float* hidden = (const float*)d_in[0];
    const float* mask   = (const float*)d_in[1];
    const float* Wq     = (const float*)d_in[2];
    const float* Wk     = (const float*)d_in[3];
    const float* Wv     = (const float*)d_in[4];
    float* out = (float*)d_out;

    float *hq, *wq, *wk, *wv, *Qp, *Kp, *Vp;
    cudaGetSymbolAddress((void**)&hq, g_hq);
    cudaGetSymbolAddress((void**)&wq, g_wq);
    cudaGetSymbolAddress((void**)&wk, g_wk);
    cudaGetSymbolAddress((void**)&wv, g_wv);
    cudaGetSymbolAddress((void**)&Qp, g_Q);
    cudaGetSymbolAddress((void**)&Kp, g_K);
    cudaGetSymbolAddress((void**)&Vp, g_V);

    init_k<<<1, 32>>>();
    absmax_k<<<512, 256>>>(hidden, 4194304, 0);
    absmax_k<<<256, 256>>>(Wq, 1048576, 1);
    absmax_k<<<256, 256>>>(Wk, 1048576, 2);
    absmax_k<<<256, 256>>>(Wv, 1048576, 3);

    quant_act_k<<<1024, 256>>>(hidden, hq, 4194304);
    quant_w_k<<<512, 256>>>(Wq, wq, 1048576, 1);
    quant_w_k<<<512, 256>>>(Wk, wk, 1048576, 2);
    quant_w_k<<<512, 256>>>(Wv, wv, 1048576, 3);

    // Q = hq@Wq^T, K = hq@Wk^T, V = hidden@Wv^T, all head-split on write
    gemm128<<<dim3(8, 32, 3), 256>>>(hq, hq, hidden, wq, wk, wv, Qp, Kp, Vp);

    cudaFuncSetAttribute(attn_k, cudaFuncAttributeMaxDynamicSharedMemorySize, 49408);
    attn_k<<<dim3(64, 16), 256, 49408>>>(Qp, Kp, Vp, mask, out);
}

// round 3
// speedup vs baseline: 2.1463x; 2.1463x over previous
#include <cuda_runtime.h>
#include <cstdint>

// ---------------- scratch (__device__ globals; no allocs allowed) ------------
__device__ int   g_hq8[1048576];     // hidden quantized int8, packed 4/int32
__device__ int   g_r8 [1048576];     // residual quantized int8, packed
__device__ int   g_wq8[262144];
__device__ int   g_wk8[262144];
__device__ int   g_wv8[262144];
__device__ float g_Q[4194304];       // [B*H, S, 64]
__device__ float g_K[4194304];
__device__ float g_V[4194304];
__device__ unsigned int g_absmax[4]; // 0:hidden 1:Wq 2:Wk 3:Wv

// ---------------- absmax / packing ------------------------------------------
__global__ void init_k() {
    if (threadIdx.x < 4) g_absmax[threadIdx.x] = 0u;
}

__global__ void absmax4_k(const float4* __restrict__ x, int n4, int slot) {
    float m = 0.f;
    for (int i = blockIdx.x * blockDim.x + threadIdx.x; i < n4; i += gridDim.x * blockDim.x) {
        float4 v = x[i];
        m = fmaxf(m, fmaxf(fmaxf(fabsf(v.x), fabsf(v.y)), fmaxf(fabsf(v.z), fabsf(v.w))));
    }
#pragma unroll
    for (int o = 16; o > 0; o >>= 1) m = fmaxf(m, __shfl_xor_sync(0xffffffffu, m, o));
    if ((threadIdx.x & 31) == 0) atomicMax(&g_absmax[slot], __float_as_uint(m));
}

__device__ __forceinline__ int pack4i(float a, float b, float c, float d) {
    int ia = (int)a, ib = (int)b, ic = (int)c, id = (int)d;
    return (ia & 0xFF) | ((ib & 0xFF) << 8) | ((ic & 0xFF) << 16) | ((id & 0xFF) << 24);
}

// hidden -> int8 (scale s = max/127) + residual int8 (scale s/254). Exact split.
__global__ void pack_act_k(const float4* __restrict__ x, int* __restrict__ q8,
                           int* __restrict__ r8, int n4) {
    float s  = fmaxf(__uint_as_float(g_absmax[0]), 1e-8f) / 127.0f;
    float s2 = s / 254.0f;
    for (int i = blockIdx.x * blockDim.x + threadIdx.x; i < n4; i += gridDim.x * blockDim.x) {
        float4 v = x[i];
        float qa = fminf(fmaxf(rintf(v.x / s), -127.f), 127.f);
        float qb = fminf(fmaxf(rintf(v.y / s), -127.f), 127.f);
        float qc = fminf(fmaxf(rintf(v.z / s), -127.f), 127.f);
        float qd = fminf(fmaxf(rintf(v.w / s), -127.f), 127.f);
        q8[i] = pack4i(qa, qb, qc, qd);
        float ra = fminf(fmaxf(rintf((v.x - qa * s) / s2), -127.f), 127.f);
        float rb = fminf(fmaxf(rintf((v.y - qb * s) / s2), -127.f), 127.f);
        float rc = fminf(fmaxf(rintf((v.z - qc * s) / s2), -127.f), 127.f);
        float rd = fminf(fmaxf(rintf((v.w - qd * s) / s2), -127.f), 127.f);
        r8[i] = pack4i(ra, rb, rc, rd);
    }
}

__global__ void pack_w_k(const float4* __restrict__ x, int* __restrict__ y, int n4, int slot) {
    float s = fmaxf(__uint_as_float(g_absmax[slot]), 1e-8f) / 7.0f;
    for (int i = blockIdx.x * blockDim.x + threadIdx.x; i < n4; i += gridDim.x * blockDim.x) {
        float4 v = x[i];
        float a = fminf(fmaxf(rintf(v.x / s), -7.f), 7.f);
        float b = fminf(fmaxf(rintf(v.y / s), -7.f), 7.f);
        float c = fminf(fmaxf(rintf(v.z / s), -7.f), 7.f);
        float d = fminf(fmaxf(rintf(v.w / s), -7.f), 7.f);
        y[i] = pack4i(a, b, c, d);
    }
}

// ---------------- int8 dp4a GEMMs -------------------------------------------
// C[m,n] = sum_d A[m,d]*W[n,d]; 128x128 tile, BK=32 int8 (8 int32), 256 thr,
// 8x8 per thread. Head-split output: O[((b*16+h)*1024+s)*64+dh].
__global__ __launch_bounds__(256) void gemm_qk(
    const int* __restrict__ A8, const int* __restrict__ Wq8, const int* __restrict__ Wk8,
    float* __restrict__ Qo, float* __restrict__ Ko)
{
    __shared__ int As[8][128];
    __shared__ int Bs[8][128];
    int z = blockIdx.z;
    const int* W = z ? Wk8 : Wq8;
    float*     O = z ? Ko : Qo;

    int tid = threadIdx.x;
    int tx = tid & 15, ty = tid >> 4;
    int m0 = blockIdx.y * 128, n0 = blockIdx.x * 128;
    int lrow = tid >> 1, lk = (tid & 1) * 4;
    const int* Ag = A8 + (m0 + lrow) * 256 + lk;
    const int* Wg = W  + (n0 + lrow) * 256 + lk;

    int c[8][8] = {};
    for (int kt = 0; kt < 256; kt += 8) {
        int4 av = *(const int4*)(Ag + kt);
        int4 wv = *(const int4*)(Wg + kt);
        As[lk + 0][lrow] = av.x; As[lk + 1][lrow] = av.y;
        As[lk + 2][lrow] = av.z; As[lk + 3][lrow] = av.w;
        Bs[lk + 0][lrow] = wv.x; Bs[lk + 1][lrow] = wv.y;
        Bs[lk + 2][lrow] = wv.z; Bs[lk + 3][lrow] = wv.w;
        __syncthreads();
#pragma unroll
        for (int k = 0; k < 8; k++) {
            int4 a0 = *(const int4*)&As[k][ty * 8];
            int4 a1 = *(const int4*)&As[k][ty * 8 + 4];
            int4 b0 = *(const int4*)&Bs[k][tx * 8];
            int4 b1 = *(const int4*)&Bs[k][tx * 8 + 4];
            int a[8] = {a0.x, a0.y, a0.z, a0.w, a1.x, a1.y, a1.z, a1.w};
            int b[8] = {b0.x, b0.y, b0.z, b0.w, b1.x, b1.y, b1.z, b1.w};
#pragma unroll
            for (int i = 0; i < 8; i++)
#pragma unroll
                for (int j = 0; j < 8; j++)
                    c[i][j] = __dp4a(a[i], b[j], c[i][j]);
        }
        __syncthreads();
    }

    float sa = fmaxf(__uint_as_float(g_absmax[0]), 1e-8f) / 127.0f;
    float sw = fmaxf(__uint_as_float(g_absmax[z + 1]), 1e-8f) / 7.0f;
    float scale = sa * sw;
#pragma unroll
    for (int i = 0; i < 8; i++) {
        int m = m0 + ty * 8 + i;
        int bb = m >> 10, s = m & 1023;
#pragma unroll
        for (int j = 0; j < 8; j++) {
            int n = n0 + tx * 8 + j;
            int h = n >> 6, dh = n & 63;
            O[((bb * 16 + h) << 16) + (s << 6) + dh] = (float)c[i][j] * scale;
        }
    }
}

// V = (q8*s + r8*s/254) @ Wv4^T: two exact integer GEMMs, combined epilogue.
__global__ __launch_bounds__(256) void gemm_v(
    const int* __restrict__ A8, const int* __restrict__ R8,
    const int* __restrict__ Wv8, float* __restrict__ Vo)
{
    __shared__ int As[8][128];
    __shared__ int Rs[8][128];
    __shared__ int Bs[8][128];

    int tid = threadIdx.x;
    int tx = tid & 15, ty = tid >> 4;
    int m0 = blockIdx.y * 128, n0 = blockIdx.x * 128;
    int lrow = tid >> 1, lk = (tid & 1) * 4;
    const int* Ag = A8  + (m0 + lrow) * 256 + lk;
    const int* Rg = R8  + (m0 + lrow) * 256 + lk;
    const int* Wg = Wv8 + (n0 + lrow) * 256 + lk;

    int c1[8][8] = {};
    int c2[8][8] = {};
    for (int kt = 0; kt < 256; kt += 8) {
        int4 av = *(const int4*)(Ag + kt);
        int4 rv = *(const int4*)(Rg + kt);
        int4 wv = *(const int4*)(Wg + kt);
        As[lk + 0][lrow] = av.x; As[lk + 1][lrow] = av.y;
        As[lk + 2][lrow] = av.z; As[lk + 3][lrow] = av.w;
        Rs[lk + 0][lrow] = rv.x; Rs[lk + 1][lrow] = rv.y;
        Rs[lk + 2][lrow] = rv.z; Rs[lk + 3][lrow] = rv.w;
        Bs[lk + 0][lrow] = wv.x; Bs[lk + 1][lrow] = wv.y;
        Bs[lk + 2][lrow] = wv.z; Bs[lk + 3][lrow] = wv.w;
        __syncthreads();
#pragma unroll
        for (int k = 0; k < 8; k++) {
            int4 a0 = *(const int4*)&As[k][ty * 8];
            int4 a1 = *(const int4*)&As[k][ty * 8 + 4];
            int4 r0 = *(const int4*)&Rs[k][ty * 8];
            int4 r1 = *(const int4*)&Rs[k][ty * 8 + 4];
            int4 b0 = *(const int4*)&Bs[k][tx * 8];
            int4 b1 = *(const int4*)&Bs[k][tx * 8 + 4];
            int a[8] = {a0.x, a0.y, a0.z, a0.w, a1.x, a1.y, a1.z, a1.w};
            int r[8] = {r0.x, r0.y, r0.z, r0.w, r1.x, r1.y, r1.z, r1.w};
            int b[8] = {b0.x, b0.y, b0.z, b0.w, b1.x, b1.y, b1.z, b1.w};
#pragma unroll
            for (int i = 0; i < 8; i++)
#pragma unroll
                for (int j = 0; j < 8; j++) {
                    c1[i][j] = __dp4a(a[i], b[j], c1[i][j]);
                    c2[i][j] = __dp4a(r[i], b[j], c2[i][j]);
                }
        }
        __syncthreads();
    }

    float sa = fmaxf(__uint_as_float(g_absmax[0]), 1e-8f) / 127.0f;
    float sv = fmaxf(__uint_as_float(g_absmax[3]), 1e-8f) / 7.0f;
    float k1 = sa * sv;
    float k2 = (sa / 254.0f) * sv;
#pragma unroll
    for (int i = 0; i < 8; i++) {
        int m = m0 + ty * 8 + i;
        int bb = m >> 10, s = m & 1023;
#pragma unroll
        for (int j = 0; j < 8; j++) {
            int n = n0 + tx * 8 + j;
            int h = n >> 6, dh = n & 63;
            Vo[((bb * 16 + h) << 16) + (s << 6) + dh] =
                fmaf((float)c2[i][j], k2, (float)c1[i][j] * k1);
        }
    }
}

// ---------------- JAX threefry2x32 noise (partitionable, key=(0,42)) --------
__device__ __forceinline__ uint32_t rotl32(uint32_t x, int r) {
    return (x << r) | (x >> (32 - r));
}

__device__ __forceinline__ void threefry2x32(uint32_t c0, uint32_t c1,
                                             uint32_t& o0, uint32_t& o1) {
    const uint32_t k0 = 0u, k1 = 42u, k2 = 0u ^ 42u ^ 0x1BD11BDAu;
    uint32_t x0 = c0 + k0, x1 = c1 + k1;
#define TF_R(r) { x0 += x1; x1 = rotl32(x1, r); x1 ^= x0; }
    TF_R(13) TF_R(15) TF_R(26) TF_R(6)
    x0 += k1; x1 += k2 + 1u;
    TF_R(17) TF_R(29) TF_R(16) TF_R(24)
    x0 += k2; x1 += k0 + 2u;
    TF_R(13) TF_R(15) TF_R(26) TF_R(6)
    x0 += k0; x1 += k1 + 3u;
    TF_R(17) TF_R(29) TF_R(16) TF_R(24)
    x0 += k1; x1 += k2 + 4u;
    TF_R(13) TF_R(15) TF_R(26) TF_R(6)
    x0 += k2; x1 += k0 + 5u;
#undef TF_R
    o0 = x0; o1 = x1;
}

__device__ __forceinline__ float noise_at(unsigned int i) {
    uint32_t o0, o1;
    threefry2x32(0u, i, o0, o1);          // c0 = hi32(counter)=0, c1 = lo32 = i
    uint32_t bits = o0 ^ o1;
    float f = __uint_as_float((bits >> 9) | 0x3f800000u) - 1.0f;
    const float lo = -0.99999994f;
    float u = fmaxf(lo, fmaf(f, 2.0f, lo));
    // w = -log1p(-u^2); t = 1-u^2 computed exactly-rounded by fma, fast log.
    float t = fmaf(-u, u, 1.0f);
    float w = -__logf(t);
    float p;
    if (w < 5.0f) {
        w = w - 2.5f;
        p = 2.81022636e-08f;
        p = fmaf(p, w, 3.43273939e-07f);
        p = fmaf(p, w, -3.5233877e-06f);
        p = fmaf(p, w, -4.39150654e-06f);
        p = fmaf(p, w, 0.00021858087f);
        p = fmaf(p, w, -0.00125372503f);
        p = fmaf(p, w, -0.00417768164f);
        p = fmaf(p, w, 0.246640727f);
        p = fmaf(p, w, 1.50140941f);
    } else {
        w = sqrtf(w) - 3.0f;
        p = -0.000200214257f;
        p = fmaf(p, w, 0.000100950558f);
        p = fmaf(p, w, 0.00134934322f);
        p = fmaf(p, w, -0.00367342844f);
        p = fmaf(p, w, 0.00573950773f);
        p = fmaf(p, w, -0.0076224613f);
        p = fmaf(p, w, 0.00943887047f);
        p = fmaf(p, w, 1.00167406f);
        p = fmaf(p, w, 2.83297682f);
    }
    return 1.41421356f * (p * u) * 0.05f;
}

// ---------------- fused flash attention (outer-product tiles) ----------------
// grid (64 bh, 16 q-tiles), 256 threads as 16x16; each thread owns 4q x 4k
// scores and a 4q x 4dh output tile. smem: Qt/Kt/Pt transposed (pad 68), Vs.
__global__ __launch_bounds__(256) void attn_k(
    const float* __restrict__ Q, const float* __restrict__ K,
    const float* __restrict__ V, const float* __restrict__ mask,
    float* __restrict__ out)
{
    extern __shared__ float sm[];
    float* Qt = sm;              // [64 d][68]  (d-major, q index)
    float* Kt = sm + 4352;       // [64 d][68]  (d-major, k index)
    float* Pt = sm + 8704;       // [64 k][68]  (k-major, q index)
    float* Vs = sm + 13056;      // [64 k][64]  (k-major, dh index)

    int bh = blockIdx.x, qt = blockIdx.y;
    int b = bh >> 4, h = bh & 15;
    int tid = threadIdx.x, tx = tid & 15, ty = tid >> 4;

    // load + transpose Q tile
    const float4* Qg = (const float4*)(Q + (bh * 1024 + qt * 64) * 64);
    for (int i = tid; i < 1024; i += 256) {
        float4 v = Qg[i];
        int q = i >> 4, d4 = (i & 15) * 4;
        Qt[(d4 + 0) * 68 + q] = v.x; Qt[(d4 + 1) * 68 + q] = v.y;
        Qt[(d4 + 2) * 68 + q] = v.z; Qt[(d4 + 3) * 68 + q] = v.w;
    }

    float m_[4], l_[4], o_[4][4];
#pragma unroll
    for (int i = 0; i < 4; i++) {
        m_[i] = -1e30f; l_[i] = 0.f;
#pragma unroll
        for (int j = 0; j < 4; j++) o_[i][j] = 0.f;
    }

    const float* maskb = mask + (b << 10);

    for (int kt = 0; kt < 16; kt++) {
        __syncthreads();
        const float4* Kg = (const float4*)(K + (bh * 1024 + kt * 64) * 64);
        const float4* Vg = (const float4*)(V + (bh * 1024 + kt * 64) * 64);
        for (int i = tid; i < 1024; i += 256) {
            float4 kv = Kg[i];
            int k = i >> 4, d4 = (i & 15) * 4;
            Kt[(d4 + 0) * 68 + k] = kv.x; Kt[(d4 + 1) * 68 + k] = kv.y;
            Kt[(d4 + 2) * 68 + k] = kv.z; Kt[(d4 + 3) * 68 + k] = kv.w;
            ((float4*)Vs)[i] = Vg[i];
        }
        __syncthreads();

        // S = Q K^T via outer products over d
        float s[4][4] = {};
#pragma unroll 16
        for (int d = 0; d < 64; d++) {
            float4 q4 = *(const float4*)&Qt[d * 68 + ty * 4];
            float4 k4 = *(const float4*)&Kt[d * 68 + tx * 4];
            float qa[4] = {q4.x, q4.y, q4.z, q4.w};
            float ka[4] = {k4.x, k4.y, k4.z, k4.w};
#pragma unroll
            for (int i = 0; i < 4; i++)
#pragma unroll
                for (int j = 0; j < 4; j++)
                    s[i][j] = fmaf(qa[i], ka[j], s[i][j]);
        }

        // scale + noise + mask
        float4 mv4 = *(const float4*)&maskb[kt * 64 + tx * 4];
        float mv[4] = {mv4.x, mv4.y, mv4.z, mv4.w};
        unsigned base = ((unsigned)bh << 20) | ((unsigned)(qt * 64 + ty * 4) << 10)
                        | (unsigned)(kt * 64 + tx * 4);
#pragma unroll
        for (int i = 0; i < 4; i++)
#pragma unroll
            for (int j = 0; j < 4; j++)
                s[i][j] = fmaf(s[i][j], 0.125f, noise_at(base + (i << 10) + j) + mv[j]);

        // online softmax (row stats across tx groups of 16 lanes)
#pragma unroll
        for (int i = 0; i < 4; i++) {
            float tm = fmaxf(fmaxf(s[i][0], s[i][1]), fmaxf(s[i][2], s[i][3]));
            tm = fmaxf(tm, __shfl_xor_sync(0xffffffffu, tm, 1));
            tm = fmaxf(tm, __shfl_xor_sync(0xffffffffu, tm, 2));
            tm = fmaxf(tm, __shfl_xor_sync(0xffffffffu, tm, 4));
            tm = fmaxf(tm, __shfl_xor_sync(0xffffffffu, tm, 8));
            float mnew = fmaxf(m_[i], tm);
            float corr = __expf(m_[i] - mnew);
            float ps = 0.f;
#pragma unroll
            for (int j = 0; j < 4; j++) { s[i][j] = __expf(s[i][j] - mnew); ps += s[i][j]; }
            ps += __shfl_xor_sync(0xffffffffu, ps, 1);
            ps += __shfl_xor_sync(0xffffffffu, ps, 2);
            ps += __shfl_xor_sync(0xffffffffu, ps, 4);
            ps += __shfl_xor_sync(0xffffffffu, ps, 8);
            l_[i] = l_[i] * corr + ps;
            m_[i] = mnew;
#pragma unroll
            for (int j = 0; j < 4; j++) o_[i][j] *= corr;
        }

        // P^T to smem (k-major)
#pragma unroll
        for (int j = 0; j < 4; j++) {
            float4 w = make_float4(s[0][j], s[1][j], s[2][j], s[3][j]);
            *(float4*)&Pt[(tx * 4 + j) * 68 + ty * 4] = w;
        }
        __syncthreads();

        // O += P V via outer products over k
#pragma unroll 8
        for (int k = 0; k < 64; k++) {
            float4 p4 = *(const float4*)&Pt[k * 68 + ty * 4];
            float4 v4 = *(const float4*)&Vs[k * 64 + tx * 4];
            float pa[4] = {p4.x, p4.y, p4.z, p4.w};
            float va[4] = {v4.x, v4.y, v4.z, v4.w};
#pragma unroll
            for (int i = 0; i < 4; i++)
#pragma unroll
                for (int j = 0; j < 4; j++)
                    o_[i][j] = fmaf(pa[i], va[j], o_[i][j]);
        }
    }

#pragma unroll
    for (int i = 0; i < 4; i++) {
        float inv = 1.0f / l_[i];
        int sI = qt * 64 + ty * 4 + i;
        float4 w = make_float4(o_[i][0] * inv, o_[i][1] * inv,
                               o_[i][2] * inv, o_[i][3] * inv);
        *(float4*)(out + ((size_t)((b << 10) + sI)) * 1024 + (h << 6) + tx * 4) = w;
    }
}

// ---------------- launch -----------------------------------------------------
extern "C" void kernel_launch(void* const* d_in, const int* in_sizes, int n_in,
                              void* d_out, int out_size) {
    const float* hidden = (const float*)d_in[0];
    const float* mask   = (const float*)d_in[1];
    const float* Wq     = (const float*)d_in[2];
    const float* Wk     = (const float*)d_in[3];
    const float* Wv     = (const float*)d_in[4];
    float* out = (float*)d_out;

    int *hq8, *r8, *wq8, *wk8, *wv8;
    float *Qp, *Kp, *Vp;
    cudaGetSymbolAddress((void**)&hq8, g_hq8);
    cudaGetSymbolAddress((void**)&r8,  g_r8);
    cudaGetSymbolAddress((void**)&wq8, g_wq8);
    cudaGetSymbolAddress((void**)&wk8, g_wk8);
    cudaGetSymbolAddress((void**)&wv8, g_wv8);
    cudaGetSymbolAddress((void**)&Qp,  g_Q);
    cudaGetSymbolAddress((void**)&Kp,  g_K);
    cudaGetSymbolAddress((void**)&Vp,  g_V);

    init_k<<<1, 32>>>();
    absmax4_k<<<512, 256>>>((const float4*)hidden, 1048576, 0);
    absmax4_k<<<128, 256>>>((const float4*)Wq, 262144, 1);
    absmax4_k<<<128, 256>>>((const float4*)Wk, 262144, 2);
    absmax4_k<<<128, 256>>>((const float4*)Wv, 262144, 3);

    pack_act_k<<<1024, 256>>>((const float4*)hidden, hq8, r8, 1048576);
    pack_w_k<<<256, 256>>>((const float4*)Wq, wq8, 262144, 1);
    pack_w_k<<<256, 256>>>((const float4*)Wk, wk8, 262144, 2);
    pack_w_k<<<256, 256>>>((const float4*)Wv, wv8, 262144, 3);

    gemm_qk<<<dim3(8, 32, 2), 256>>>(hq8, wq8, wk8, Qp, Kp);
    gemm_v<<<dim3(8, 32), 256>>>(hq8, r8, wv8, Vp);

    cudaFuncSetAttribute(attn_k, cudaFuncAttributeMaxDynamicSharedMemorySize, 68608);
    attn_k<<<dim3(64, 16), 256, 68608>>>(Qp, Kp, Vp, mask, out);
}